// round 1
// baseline (speedup 1.0000x reference)
#include <cuda_runtime.h>
#include <cstdint>

#define NN 100000
#define NE 3200000
#define FIN 512
#define H   16
#define FOUT 128
#define NC  3

// ---------------- scratch (no allocations allowed) ----------------
__device__ float4 g_P1[NN * 4];    // layer-1 projected (pre-aggregation), 16 f/node
__device__ float4 g_agg1[NN * 4];  // layer-1 aggregation target
__device__ float4 g_P2[NN * 4];    // relu(...)*norm_src for layer 2
__device__ float4 g_agg2[NN * 4];  // layer-2 aggregation target
__device__ int    g_deg_out[NN];
__device__ int    g_deg_in[NN];
__device__ float  g_Wc[H * NC];    // W2 @ Wfc  (16x3)
__device__ float  g_bc[NC];        // b2 @ Wfc + bfc
__device__ int    g_is64;

// ---------------- helpers ----------------
__device__ __forceinline__ int eidx(const void* p, int e, int is64) {
    if (is64) return (int)__ldcs(((const long long*)p) + e);
    return __ldcs(((const int*)p) + e);
}

// ---------------- index dtype detection ----------------
// int64 indices < 100000 => every odd 32-bit word is zero. For int32 data the
// odd words are independent random indices (P(zero)=1e-5 each).
__global__ void k_detect(const unsigned* __restrict__ w) {
    if (threadIdx.x == 0) {
        int is64 = 1;
        #pragma unroll 1
        for (int i = 0; i < 256; i++) {
            if (w[2 * i + 1] != 0u) { is64 = 0; break; }
        }
        g_is64 = is64;
    }
}

// ---------------- fused W2@Wfc ----------------
__global__ void k_wc(const float* __restrict__ W2, const float* __restrict__ b2,
                     const float* __restrict__ Wfc, const float* __restrict__ bfc) {
    int t = threadIdx.x;
    if (t < H * NC) {
        int k = t / NC, c = t % NC;
        float s = 0.f;
        #pragma unroll 4
        for (int j = 0; j < FOUT; j++) s += W2[k * FOUT + j] * Wfc[j * NC + c];
        g_Wc[t] = s;
    }
    if (t < NC) {
        float s = bfc[t];
        #pragma unroll 4
        for (int j = 0; j < FOUT; j++) s += b2[j] * Wfc[j * NC + t];
        g_bc[t] = s;
    }
}

// ---------------- degrees ----------------
__global__ void k_zero_deg() {
    int i = blockIdx.x * blockDim.x + threadIdx.x;
    if (i < NN) { g_deg_out[i] = 0; g_deg_in[i] = 0; }
}

__global__ void k_degree(const void* __restrict__ src, const void* __restrict__ dst) {
    int e = blockIdx.x * blockDim.x + threadIdx.x;
    if (e >= NE) return;
    int is64 = g_is64;
    atomicAdd(&g_deg_out[eidx(src, e, is64)], 1);
    atomicAdd(&g_deg_in[eidx(dst, e, is64)], 1);
}

// ---------------- layer-1 GEMM: P1 = norm_src * (feat @ W1), also zero agg1 ----
// warp handles 4 rows; W1 transposed into smem so WsT[k*512+i] hits bank i%32
// == lane -> conflict-free.
__global__ void __launch_bounds__(256) k_gemm1(const float* __restrict__ feat,
                                               const float* __restrict__ W1) {
    __shared__ float WsT[H * FIN];  // [k][i]
    for (int t = threadIdx.x; t < FIN * H; t += 256) {
        int i = t / H, k = t % H;
        WsT[k * FIN + i] = W1[t];
    }
    __syncthreads();

    int warp = threadIdx.x >> 5, lane = threadIdx.x & 31;
    int row0 = (blockIdx.x * 8 + warp) * 4;
    if (row0 >= NN) return;

    float acc[4][16];
    #pragma unroll
    for (int r = 0; r < 4; r++)
        #pragma unroll
        for (int k = 0; k < 16; k++) acc[r][k] = 0.f;

    #pragma unroll
    for (int m = 0; m < 16; m++) {
        int i = lane + 32 * m;
        float w[16];
        #pragma unroll
        for (int k = 0; k < 16; k++) w[k] = WsT[k * FIN + i];
        #pragma unroll
        for (int r = 0; r < 4; r++) {
            int row = row0 + r;
            float xv = (row < NN) ? __ldcs(feat + (size_t)row * FIN + i) : 0.f;
            #pragma unroll
            for (int k = 0; k < 16; k++) acc[r][k] = fmaf(xv, w[k], acc[r][k]);
        }
    }

    // warp reduce each accumulator
    #pragma unroll
    for (int r = 0; r < 4; r++)
        #pragma unroll
        for (int k = 0; k < 16; k++)
            #pragma unroll
            for (int off = 16; off > 0; off >>= 1)
                acc[r][k] += __shfl_xor_sync(0xffffffffu, acc[r][k], off);

    if (lane == 0) {
        #pragma unroll
        for (int r = 0; r < 4; r++) {
            int row = row0 + r;
            if (row >= NN) break;
            float ns = rsqrtf(fmaxf((float)g_deg_out[row], 1.f));
            float4* p = &g_P1[row * 4];
            #pragma unroll
            for (int c = 0; c < 4; c++) {
                p[c] = make_float4(acc[r][4 * c + 0] * ns, acc[r][4 * c + 1] * ns,
                                   acc[r][4 * c + 2] * ns, acc[r][4 * c + 3] * ns);
                g_agg1[row * 4 + c] = make_float4(0.f, 0.f, 0.f, 0.f);
            }
        }
    }
}

// ---------------- edge scatter: agg[dst] += P[src], 16 floats / edge ----------
template <int PASS>
__global__ void __launch_bounds__(256) k_scatter(const void* __restrict__ src,
                                                 const void* __restrict__ dst) {
    int e = blockIdx.x * blockDim.x + threadIdx.x;
    if (e >= NE) return;
    int is64 = g_is64;
    int s = eidx(src, e, is64);
    int d = eidx(dst, e, is64);
    const float4* ps = (PASS == 1 ? (const float4*)g_P1 : (const float4*)g_P2) + s * 4;
    float4*       pd = (PASS == 1 ? g_agg1 : g_agg2) + d * 4;
    #pragma unroll
    for (int c = 0; c < 4; c++) {
        float4 v = __ldg(ps + c);
        asm volatile("red.global.add.v4.f32 [%0], {%1, %2, %3, %4};"
                     :: "l"(pd + c), "f"(v.x), "f"(v.y), "f"(v.z), "f"(v.w)
                     : "memory");
    }
}

// ---------------- layer-1 epilogue: P2 = relu(agg1*nd + b1)*ns; zero agg2 -----
__global__ void k_mid(const float* __restrict__ b1) {
    int n = blockIdx.x * blockDim.x + threadIdx.x;
    if (n >= NN) return;
    float nd = rsqrtf(fmaxf((float)g_deg_in[n], 1.f));
    float ns = rsqrtf(fmaxf((float)g_deg_out[n], 1.f));
    #pragma unroll
    for (int c = 0; c < 4; c++) {
        float4 a = g_agg1[n * 4 + c];
        float4 b = ((const float4*)b1)[c];
        float4 o;
        o.x = fmaxf(fmaf(a.x, nd, b.x), 0.f) * ns;
        o.y = fmaxf(fmaf(a.y, nd, b.y), 0.f) * ns;
        o.z = fmaxf(fmaf(a.z, nd, b.z), 0.f) * ns;
        o.w = fmaxf(fmaf(a.w, nd, b.w), 0.f) * ns;
        g_P2[n * 4 + c] = o;
        g_agg2[n * 4 + c] = make_float4(0.f, 0.f, 0.f, 0.f);
    }
}

// ---------------- final: out = nd * (agg2 @ Wc) + bc --------------------------
__global__ void k_final(float* __restrict__ out) {
    int n = blockIdx.x * blockDim.x + threadIdx.x;
    if (n >= NN) return;
    float nd = rsqrtf(fmaxf((float)g_deg_in[n], 1.f));
    float a[16];
    #pragma unroll
    for (int c = 0; c < 4; c++) {
        float4 v = g_agg2[n * 4 + c];
        a[4 * c + 0] = v.x; a[4 * c + 1] = v.y; a[4 * c + 2] = v.z; a[4 * c + 3] = v.w;
    }
    float o0 = g_bc[0], o1 = g_bc[1], o2 = g_bc[2];
    #pragma unroll
    for (int k = 0; k < 16; k++) {
        float z = a[k] * nd;
        o0 = fmaf(z, g_Wc[k * 3 + 0], o0);
        o1 = fmaf(z, g_Wc[k * 3 + 1], o1);
        o2 = fmaf(z, g_Wc[k * 3 + 2], o2);
    }
    out[n * 3 + 0] = o0;
    out[n * 3 + 1] = o1;
    out[n * 3 + 2] = o2;
}

// ---------------- launch ----------------
extern "C" void kernel_launch(void* const* d_in, const int* in_sizes, int n_in,
                              void* d_out, int out_size) {
    const float* features = (const float*)d_in[0];
    const void*  src      = d_in[1];
    const void*  dst      = d_in[2];
    const float* W1       = (const float*)d_in[3];
    const float* b1       = (const float*)d_in[4];
    const float* W2       = (const float*)d_in[5];
    const float* b2       = (const float*)d_in[6];
    const float* Wfc      = (const float*)d_in[7];
    const float* bfc      = (const float*)d_in[8];
    float* out = (float*)d_out;

    (void)in_sizes; (void)n_in; (void)out_size;

    const int EB = (NE + 255) / 256;
    const int NB = (NN + 255) / 256;

    k_wc<<<1, 64>>>(W2, b2, Wfc, bfc);
    k_detect<<<1, 32>>>((const unsigned*)src);
    k_zero_deg<<<NB, 256>>>();
    k_degree<<<EB, 256>>>(src, dst);
    k_gemm1<<<(NN + 31) / 32, 256>>>(features, W1);
    k_scatter<1><<<EB, 256>>>(src, dst);
    k_mid<<<NB, 256>>>(b1);
    k_scatter<2><<<EB, 256>>>(src, dst);
    k_final<<<NB, 256>>>(out);
}